// round 13
// baseline (speedup 1.0000x reference)
#include <cuda_runtime.h>
#include <cuda_fp16.h>
#include <math_constants.h>
#include <stdint.h>

#define B_   8
#define T_   4
#define De_  128
#define Do_  512
#define HW_  1024
#define THW_ 4096

#define SCALE_ 0.08838834764831843f   // 1/sqrt(128)

// ---------------------------------------------------------------------------
// Static scratch: fp16 operands (K-major) + softmax column sums.
// ---------------------------------------------------------------------------
__device__ __align__(256) __half g_miT[(size_t)32 * 1024 * 128];  // [bt][m][k]
__device__ __align__(256) __half g_qiT[(size_t)8 * 1024 * 128];   // [b][n][k] pre-scaled
__device__ __align__(256) __half g_mo[(size_t)8 * 512 * 4096];    // [b][d][k]
__device__ __align__(256) __half g_pT[(size_t)8 * 1024 * 4096];   // [b][n][k]
__device__ __align__(256) float  g_S[(size_t)B_ * HW_];           // softmax sums

// ---------------------------------------------------------------------------
// Conversion kernels
// ---------------------------------------------------------------------------
__global__ __launch_bounds__(256) void conv_mo_kernel(const float4* __restrict__ src) {
    const size_t i = (size_t)blockIdx.x * 256 + threadIdx.x;
    if (i >= (size_t)B_ * Do_ * THW_ / 4) return;
    const float4 v = src[i];
    __half2* dst = (__half2*)g_mo;
    dst[i * 2 + 0] = __halves2half2(__float2half(v.x), __float2half(v.y));
    dst[i * 2 + 1] = __halves2half2(__float2half(v.z), __float2half(v.w));
}

// Transpose + convert: src [z][R][C] fp32 -> dst [z][C][R] fp16
__global__ __launch_bounds__(256) void tconv_kernel(const float* __restrict__ src,
                                                    int R, int C, float scale, int which) {
    __shared__ float tile[32][33];
    __half* dst = (which == 0) ? g_miT : g_qiT;

    const size_t bo = (size_t)blockIdx.z * R * C;
    const int r0 = blockIdx.y * 32, c0 = blockIdx.x * 32;
    const int x = threadIdx.x, y = threadIdx.y;   // 32 x 8

    #pragma unroll
    for (int i = 0; i < 4; ++i)
        tile[y + 8 * i][x] = src[bo + (size_t)(r0 + y + 8 * i) * C + c0 + x];
    __syncthreads();

    #pragma unroll
    for (int i = 0; i < 4; ++i) {
        const float v = tile[x][y + 8 * i] * scale;
        dst[bo + (size_t)(c0 + y + 8 * i) * R + r0 + x] = __float2half(v);
    }
}

// Zero the softmax-sum buffer (must run before GEMM1 each call).
__global__ __launch_bounds__(256) void zero_s_kernel() {
    g_S[blockIdx.x * 256 + threadIdx.x] = 0.f;
}

// ---------------------------------------------------------------------------
// fp16 GEMM: mma.sync m16n8k16 + ldmatrix.x4 + 3-stage cp.async, KC=64.
// CTA tile 128x128, 8 warps (2m x 4n), warp tile 64x32.
//   C[m,n] = sum_k A[m,k]*B[n,k], fp32 accum.
// which: 0 = GEMM1 (A=miT, B=qiT; epilogue = exp + column-sum accumulate)
//        1 = GEMM2 (A=mo, B=pT; plain epilogue)
// ---------------------------------------------------------------------------
#define KC       64
#define ROWB     144                     // 128B data + 16B pad (conflict-free)
#define TILE_SB  (128 * ROWB)            // 18432 B per tile
#define BUF_SB   (2 * TILE_SB)           // A, B
#define NSTAGE   3
#define GSMEM    (NSTAGE * BUF_SB)       // 110592 B -> 2 CTAs/SM

static __device__ __forceinline__ void mma16816(float* c, const uint32_t* a,
                                                uint32_t b0, uint32_t b1) {
    asm volatile(
        "mma.sync.aligned.m16n8k16.row.col.f32.f16.f16.f32 "
        "{%0,%1,%2,%3}, {%4,%5,%6,%7}, {%8,%9}, {%0,%1,%2,%3};"
        : "+f"(c[0]), "+f"(c[1]), "+f"(c[2]), "+f"(c[3])
        : "r"(a[0]), "r"(a[1]), "r"(a[2]), "r"(a[3]), "r"(b0), "r"(b1));
}
static __device__ __forceinline__ void ldmx4(uint32_t* r, uint32_t addr) {
    asm volatile("ldmatrix.sync.aligned.m8n8.x4.shared.b16 {%0,%1,%2,%3}, [%4];"
                 : "=r"(r[0]), "=r"(r[1]), "=r"(r[2]), "=r"(r[3]) : "r"(addr));
}
static __device__ __forceinline__ void cpa16(uint32_t dst, const void* src) {
    asm volatile("cp.async.cg.shared.global [%0], [%1], 16;" :: "r"(dst), "l"(src));
}
static __device__ __forceinline__ void cpa_commit() {
    asm volatile("cp.async.commit_group;" ::: "memory");
}
template <int N> static __device__ __forceinline__ void cpa_wait() {
    asm volatile("cp.async.wait_group %0;" :: "n"(N) : "memory");
}

__global__ __launch_bounds__(256, 2) void gemm_fp16(
    float* __restrict__ cbase, int K, int ldc,
    unsigned long long strideA, unsigned long long strideB,
    unsigned long long strideC, int bshift, int which)
{
    extern __shared__ __align__(16) char smem[];
    const uint32_t sb = (uint32_t)__cvta_generic_to_shared(smem);

    const int tid  = threadIdx.x;
    const int wid  = tid >> 5, lane = tid & 31;
    const int gid  = lane >> 2, tig = lane & 3;
    const int wm0  = (wid & 1) * 64;
    const int wn0  = (wid >> 1) * 32;
    const int z    = blockIdx.z;
    const int m0   = blockIdx.x * 128;
    const int n0   = blockIdx.y * 128;

    const __half* A  = (which == 0) ? g_miT : g_mo;
    const __half* Bm = (which == 0) ? g_qiT : g_pT;

    // loader: thread t -> row (t>>3)+32*i, 16B col chunk (t&7)
    const int lrow = tid >> 3;                       // 0..31
    const int lce  = (tid & 7) * 8;                  // elem offset (0..56)
    const uint32_t sdst = (uint32_t)lrow * ROWB + (tid & 7) * 16;

    const __half* gA = A  + (size_t)z * strideA + (size_t)(m0 + lrow) * K + lce;
    const __half* gB = Bm + (size_t)(z >> bshift) * strideB + (size_t)(n0 + lrow) * K + lce;
    const size_t r32 = (size_t)32 * K;

    const uint32_t aoff = (uint32_t)(wm0 + (lane & 15)) * ROWB + (lane >> 4) * 16;
    const uint32_t boff = (uint32_t)(wn0 + (lane & 7) + (lane >> 4) * 8) * ROWB
                        + ((lane >> 3) & 1) * 16;

    float* C = cbase + (size_t)z * strideC + (size_t)m0 * ldc + n0;

    float acc[4][4][4];
    #pragma unroll
    for (int i = 0; i < 4; ++i)
        #pragma unroll
        for (int j = 0; j < 4; ++j)
            #pragma unroll
            for (int q = 0; q < 4; ++q) acc[i][j][q] = 0.f;

    const int nch = K / KC;   // GEMM1: 2, GEMM2: 64

    #pragma unroll
    for (int s = 0; s < NSTAGE - 1; ++s) {
        const uint32_t db = sb + (uint32_t)s * BUF_SB;
        const int o = s * KC;
        #pragma unroll
        for (int i = 0; i < 4; ++i) {
            cpa16(db + sdst + (uint32_t)i * (32 * ROWB), gA + o + i * r32);
            cpa16(db + TILE_SB + sdst + (uint32_t)i * (32 * ROWB), gB + o + i * r32);
        }
        cpa_commit();
    }

    int cbuf = 0;
    for (int ch = 0; ch < nch; ++ch) {
        cpa_wait<NSTAGE - 2>();
        __syncthreads();

        if (ch + NSTAGE - 1 < nch) {
            int ibuf = cbuf + NSTAGE - 1;
            if (ibuf >= NSTAGE) ibuf -= NSTAGE;
            const uint32_t db = sb + (uint32_t)ibuf * BUF_SB;
            const int o = (ch + NSTAGE - 1) * KC;
            #pragma unroll
            for (int i = 0; i < 4; ++i) {
                cpa16(db + sdst + (uint32_t)i * (32 * ROWB), gA + o + i * r32);
                cpa16(db + TILE_SB + sdst + (uint32_t)i * (32 * ROWB), gB + o + i * r32);
            }
        }
        cpa_commit();

        const uint32_t cb = sb + (uint32_t)cbuf * BUF_SB;
        if (++cbuf == NSTAGE) cbuf = 0;
        const uint32_t a_b = cb + aoff;
        const uint32_t b_b = cb + TILE_SB + boff;

        #pragma unroll
        for (int s = 0; s < 4; ++s) {
            uint32_t bf[4][2];
            #pragma unroll
            for (int g = 0; g < 2; ++g) {
                uint32_t r[4];
                ldmx4(r, b_b + (uint32_t)g * (16 * ROWB) + s * 32);
                bf[2 * g][0] = r[0]; bf[2 * g][1] = r[1];
                bf[2 * g + 1][0] = r[2]; bf[2 * g + 1][1] = r[3];
            }
            #pragma unroll
            for (int mf = 0; mf < 4; ++mf) {
                uint32_t af[4];
                ldmx4(af, a_b + (uint32_t)mf * (16 * ROWB) + s * 32);
                #pragma unroll
                for (int nf = 0; nf < 4; ++nf)
                    mma16816(acc[mf][nf], af, bf[nf][0], bf[nf][1]);
            }
        }
    }

    if (which == 0) {
        // GEMM1 epilogue: write exp(score), accumulate column sums into g_S.
        __shared__ float scol[128];
        #pragma unroll
        for (int i = tid; i < 128; i += 256) scol[i] = 0.f;
        __syncthreads();

        float csum[8];
        #pragma unroll
        for (int j = 0; j < 8; ++j) csum[j] = 0.f;

        #pragma unroll
        for (int mf = 0; mf < 4; ++mf) {
            const int rr = wm0 + mf * 16 + gid;
            #pragma unroll
            for (int nf = 0; nf < 4; ++nf) {
                const int cc = wn0 + nf * 8 + 2 * tig;
                float e0 = __expf(acc[mf][nf][0]);
                float e1 = __expf(acc[mf][nf][1]);
                float e2 = __expf(acc[mf][nf][2]);
                float e3 = __expf(acc[mf][nf][3]);
                csum[nf * 2 + 0] += e0 + e2;
                csum[nf * 2 + 1] += e1 + e3;
                float2 v0 = make_float2(e0, e1);
                float2 v1 = make_float2(e2, e3);
                *(float2*)(C + (size_t)rr * ldc + cc)       = v0;
                *(float2*)(C + (size_t)(rr + 8) * ldc + cc) = v1;
            }
        }
        #pragma unroll
        for (int nf = 0; nf < 4; ++nf) {
            atomicAdd(&scol[wn0 + nf * 8 + 2 * tig],     csum[nf * 2 + 0]);
            atomicAdd(&scol[wn0 + nf * 8 + 2 * tig + 1], csum[nf * 2 + 1]);
        }
        __syncthreads();
        if (tid < 128)
            atomicAdd(&g_S[(size_t)(z >> bshift) * HW_ + n0 + tid], scol[tid]);
    } else {
        #pragma unroll
        for (int mf = 0; mf < 4; ++mf) {
            const int rr = wm0 + mf * 16 + gid;
            #pragma unroll
            for (int nf = 0; nf < 4; ++nf) {
                const int cc = wn0 + nf * 8 + 2 * tig;
                float2 v0, v1;
                v0.x = acc[mf][nf][0]; v0.y = acc[mf][nf][1];
                v1.x = acc[mf][nf][2]; v1.y = acc[mf][nf][3];
                *(float2*)(C + (size_t)rr * ldc + cc)       = v0;
                *(float2*)(C + (size_t)(rr + 8) * ldc + cc) = v1;
            }
        }
    }
}

// ---------------------------------------------------------------------------
// Normalize + transpose/convert: p *= 1/S (in place) AND emit pT fp16.
// Single pass (exp already applied by GEMM1 epilogue).
// Block: 256 threads, 32 columns (n) x 8-way k split.
// ---------------------------------------------------------------------------
__global__ __launch_bounds__(256) void normalize_pt_kernel(float* __restrict__ p)
{
    const int b  = blockIdx.y;
    const int n0 = blockIdx.x * 32;
    float* col = p + (size_t)b * THW_ * HW_ + n0;

    const int tid = threadIdx.x;
    const int nn = tid & 31;
    const int kk = tid >> 5;   // 0..7

    const float rinv = 1.0f / g_S[(size_t)b * HW_ + n0 + nn];

    __shared__ __align__(16) __half thi[32][72];

    const int wrow = tid >> 3;            // 0..31 (n row for output)
    const int wseg = (tid & 7) * 8;       // k segment within 64-chunk
    const size_t gbase = ((size_t)b * HW_ + n0) * THW_;

    for (int k0 = 0; k0 < THW_; k0 += 64) {
        __align__(16) __half hbuf[8];
        #pragma unroll
        for (int j = 0; j < 8; ++j) {
            const int k = k0 + kk * 8 + j;
            const size_t idx = (size_t)k * HW_ + nn;
            const float e = col[idx] * rinv;
            col[idx] = e;
            hbuf[j] = __float2half(e);
        }
        *(uint4*)&thi[nn][kk * 8] = *(const uint4*)hbuf;
        __syncthreads();

        *(uint4*)(g_pT + gbase + (size_t)wrow * THW_ + k0 + wseg) =
            *(const uint4*)&thi[wrow][wseg];
        __syncthreads();
    }
}

// ---------------------------------------------------------------------------
// Concat epilogue: mem_out[b, 512:1024, :] = q_out[b]
// ---------------------------------------------------------------------------
__global__ __launch_bounds__(256) void copy_qout_kernel(
    const float4* __restrict__ q_out, float4* __restrict__ mem_out)
{
    const int i = blockIdx.x * 256 + threadIdx.x;
    const int per_b = Do_ * HW_ / 4;
    if (i >= B_ * per_b) return;
    const int b = i / per_b;
    const int r = i - b * per_b;
    mem_out[(size_t)b * (2 * Do_ * HW_ / 4) + per_b + r] = q_out[i];
}

// ---------------------------------------------------------------------------
extern "C" void kernel_launch(void* const* d_in, const int* in_sizes, int n_in,
                              void* d_out, int out_size)
{
    const float* m_in  = (const float*)d_in[0];
    const float* m_out = (const float*)d_in[1];
    const float* q_in  = (const float*)d_in[2];
    const float* q_out = (const float*)d_in[3];

    float* out     = (float*)d_out;
    float* mem_out = out;
    float* p       = out + (size_t)B_ * 2 * Do_ * HW_;

    cudaFuncSetAttribute(gemm_fp16, cudaFuncAttributeMaxDynamicSharedMemorySize, GSMEM);

    // 0. zero softmax-sum buffer
    zero_s_kernel<<<B_ * HW_ / 256, 256>>>();

    // 1. convert operands (transpose to K-major where needed)
    conv_mo_kernel<<<(B_ * Do_ * THW_ / 4 + 255) / 256, 256>>>((const float4*)m_out);
    dim3 tb(32, 8);
    tconv_kernel<<<dim3(32, 4, 32), tb>>>(m_in, 128, 1024, 1.0f, 0);
    tconv_kernel<<<dim3(32, 4, 8),  tb>>>(q_in, 128, 1024, SCALE_, 1);

    // 2. GEMM1: exp(scores) -> p region; column sums -> g_S
    gemm_fp16<<<dim3(8, 8, 32), 256, GSMEM>>>(
        p, 128, 1024,
        (unsigned long long)1024 * 128, (unsigned long long)1024 * 128,
        (unsigned long long)HW_ * HW_, 2, 0);

    // 3. normalize (in place) + pT convert/transpose (single pass)
    dim3 gs(HW_ / 32, B_);
    normalize_pt_kernel<<<gs, 256>>>(p);

    // 4. GEMM2: mem -> mem_out channels [0:512]
    gemm_fp16<<<dim3(4, 8, 8), 256, GSMEM>>>(
        mem_out, 4096, 1024,
        (unsigned long long)512 * 4096, (unsigned long long)1024 * 4096,
        (unsigned long long)1024 * 1024, 0, 1);

    // 5. concat q_out
    copy_qout_kernel<<<(B_ * Do_ * HW_ / 4 + 255) / 256, 256>>>(
        (const float4*)q_out, (float4*)mem_out);
}

// round 14
// speedup vs baseline: 1.0029x; 1.0029x over previous
#include <cuda_runtime.h>
#include <cuda_fp16.h>
#include <math_constants.h>
#include <stdint.h>

#define B_   8
#define T_   4
#define De_  128
#define Do_  512
#define HW_  1024
#define THW_ 4096

#define SCALE_ 0.08838834764831843f   // 1/sqrt(128)

// ---------------------------------------------------------------------------
// Static scratch: fp16 operands (K-major) + softmax column sums.
// ---------------------------------------------------------------------------
__device__ __align__(256) __half g_miT[(size_t)32 * 1024 * 128];  // [bt][m][k]
__device__ __align__(256) __half g_qiT[(size_t)8 * 1024 * 128];   // [b][n][k] pre-scaled
__device__ __align__(256) __half g_mo[(size_t)8 * 512 * 4096];    // [b][d][k]
__device__ __align__(256) __half g_pT[(size_t)8 * 1024 * 4096];   // [b][n][k]
__device__ __align__(256) float  g_S[(size_t)B_ * HW_];           // softmax sums

// ---------------------------------------------------------------------------
// Conversion kernels
// ---------------------------------------------------------------------------
__global__ __launch_bounds__(256) void conv_mo_kernel(const float4* __restrict__ src) {
    const size_t i = (size_t)blockIdx.x * 256 + threadIdx.x;
    if (i >= (size_t)B_ * Do_ * THW_ / 4) return;
    const float4 v = src[i];
    __half2* dst = (__half2*)g_mo;
    dst[i * 2 + 0] = __halves2half2(__float2half(v.x), __float2half(v.y));
    dst[i * 2 + 1] = __halves2half2(__float2half(v.z), __float2half(v.w));
}

// Transpose + convert: src [z][R][C] fp32 -> dst [z][C][R] fp16
__global__ __launch_bounds__(256) void tconv_kernel(const float* __restrict__ src,
                                                    int R, int C, float scale, int which) {
    __shared__ float tile[32][33];
    __half* dst = (which == 0) ? g_miT : g_qiT;

    const size_t bo = (size_t)blockIdx.z * R * C;
    const int r0 = blockIdx.y * 32, c0 = blockIdx.x * 32;
    const int x = threadIdx.x, y = threadIdx.y;   // 32 x 8

    #pragma unroll
    for (int i = 0; i < 4; ++i)
        tile[y + 8 * i][x] = src[bo + (size_t)(r0 + y + 8 * i) * C + c0 + x];
    __syncthreads();

    #pragma unroll
    for (int i = 0; i < 4; ++i) {
        const float v = tile[x][y + 8 * i] * scale;
        dst[bo + (size_t)(c0 + y + 8 * i) * R + r0 + x] = __float2half(v);
    }
}

// Zero the softmax-sum buffer (must run before GEMM1 each call).
__global__ __launch_bounds__(256) void zero_s_kernel() {
    g_S[blockIdx.x * 256 + threadIdx.x] = 0.f;
}

// ---------------------------------------------------------------------------
// fp16 GEMM: mma.sync m16n8k16 + ldmatrix.x4 + 3-stage cp.async, KC=64.
// CTA tile 128x128, 8 warps (2m x 4n), warp tile 64x32.
//   C[m,n] = sum_k A[m,k]*B[n,k], fp32 accum.
// which: 0 = GEMM1 (A=miT, B=qiT; epilogue = exp + column-sum accumulate)
//        1 = GEMM2 (A=mo, B=pT; plain epilogue)
// ---------------------------------------------------------------------------
#define KC       64
#define ROWB     144                     // 128B data + 16B pad (conflict-free)
#define TILE_SB  (128 * ROWB)            // 18432 B per tile
#define BUF_SB   (2 * TILE_SB)           // A, B
#define NSTAGE   3
#define GSMEM    (NSTAGE * BUF_SB)       // 110592 B -> 2 CTAs/SM

static __device__ __forceinline__ void mma16816(float* c, const uint32_t* a,
                                                uint32_t b0, uint32_t b1) {
    asm volatile(
        "mma.sync.aligned.m16n8k16.row.col.f32.f16.f16.f32 "
        "{%0,%1,%2,%3}, {%4,%5,%6,%7}, {%8,%9}, {%0,%1,%2,%3};"
        : "+f"(c[0]), "+f"(c[1]), "+f"(c[2]), "+f"(c[3])
        : "r"(a[0]), "r"(a[1]), "r"(a[2]), "r"(a[3]), "r"(b0), "r"(b1));
}
static __device__ __forceinline__ void ldmx4(uint32_t* r, uint32_t addr) {
    asm volatile("ldmatrix.sync.aligned.m8n8.x4.shared.b16 {%0,%1,%2,%3}, [%4];"
                 : "=r"(r[0]), "=r"(r[1]), "=r"(r[2]), "=r"(r[3]) : "r"(addr));
}
static __device__ __forceinline__ void cpa16(uint32_t dst, const void* src) {
    asm volatile("cp.async.cg.shared.global [%0], [%1], 16;" :: "r"(dst), "l"(src));
}
static __device__ __forceinline__ void cpa_commit() {
    asm volatile("cp.async.commit_group;" ::: "memory");
}
template <int N> static __device__ __forceinline__ void cpa_wait() {
    asm volatile("cp.async.wait_group %0;" :: "n"(N) : "memory");
}

__global__ __launch_bounds__(256, 2) void gemm_fp16(
    float* __restrict__ cbase, int K, int ldc,
    unsigned long long strideA, unsigned long long strideB,
    unsigned long long strideC, int bshift, int which)
{
    extern __shared__ __align__(16) char smem[];
    const uint32_t sb = (uint32_t)__cvta_generic_to_shared(smem);

    const int tid  = threadIdx.x;
    const int wid  = tid >> 5, lane = tid & 31;
    const int gid  = lane >> 2, tig = lane & 3;
    const int wm0  = (wid & 1) * 64;
    const int wn0  = (wid >> 1) * 32;
    const int z    = blockIdx.z;
    const int m0   = blockIdx.x * 128;
    const int n0   = blockIdx.y * 128;

    const __half* A  = (which == 0) ? g_miT : g_mo;
    const __half* Bm = (which == 0) ? g_qiT : g_pT;

    // loader: thread t -> row (t>>3)+32*i, 16B col chunk (t&7)
    const int lrow = tid >> 3;                       // 0..31
    const int lce  = (tid & 7) * 8;                  // elem offset (0..56)
    const uint32_t sdst = (uint32_t)lrow * ROWB + (tid & 7) * 16;

    const __half* gA = A  + (size_t)z * strideA + (size_t)(m0 + lrow) * K + lce;
    const __half* gB = Bm + (size_t)(z >> bshift) * strideB + (size_t)(n0 + lrow) * K + lce;
    const size_t r32 = (size_t)32 * K;

    const uint32_t aoff = (uint32_t)(wm0 + (lane & 15)) * ROWB + (lane >> 4) * 16;
    const uint32_t boff = (uint32_t)(wn0 + (lane & 7) + (lane >> 4) * 8) * ROWB
                        + ((lane >> 3) & 1) * 16;

    float* C = cbase + (size_t)z * strideC + (size_t)m0 * ldc + n0;

    float acc[4][4][4];
    #pragma unroll
    for (int i = 0; i < 4; ++i)
        #pragma unroll
        for (int j = 0; j < 4; ++j)
            #pragma unroll
            for (int q = 0; q < 4; ++q) acc[i][j][q] = 0.f;

    const int nch = K / KC;   // GEMM1: 2, GEMM2: 64

    #pragma unroll
    for (int s = 0; s < NSTAGE - 1; ++s) {
        const uint32_t db = sb + (uint32_t)s * BUF_SB;
        const int o = s * KC;
        #pragma unroll
        for (int i = 0; i < 4; ++i) {
            cpa16(db + sdst + (uint32_t)i * (32 * ROWB), gA + o + i * r32);
            cpa16(db + TILE_SB + sdst + (uint32_t)i * (32 * ROWB), gB + o + i * r32);
        }
        cpa_commit();
    }

    int cbuf = 0;
    for (int ch = 0; ch < nch; ++ch) {
        cpa_wait<NSTAGE - 2>();
        __syncthreads();

        if (ch + NSTAGE - 1 < nch) {
            int ibuf = cbuf + NSTAGE - 1;
            if (ibuf >= NSTAGE) ibuf -= NSTAGE;
            const uint32_t db = sb + (uint32_t)ibuf * BUF_SB;
            const int o = (ch + NSTAGE - 1) * KC;
            #pragma unroll
            for (int i = 0; i < 4; ++i) {
                cpa16(db + sdst + (uint32_t)i * (32 * ROWB), gA + o + i * r32);
                cpa16(db + TILE_SB + sdst + (uint32_t)i * (32 * ROWB), gB + o + i * r32);
            }
        }
        cpa_commit();

        const uint32_t cb = sb + (uint32_t)cbuf * BUF_SB;
        if (++cbuf == NSTAGE) cbuf = 0;
        const uint32_t a_b = cb + aoff;
        const uint32_t b_b = cb + TILE_SB + boff;

        #pragma unroll
        for (int s = 0; s < 4; ++s) {
            uint32_t bf[4][2];
            #pragma unroll
            for (int g = 0; g < 2; ++g) {
                uint32_t r[4];
                ldmx4(r, b_b + (uint32_t)g * (16 * ROWB) + s * 32);
                bf[2 * g][0] = r[0]; bf[2 * g][1] = r[1];
                bf[2 * g + 1][0] = r[2]; bf[2 * g + 1][1] = r[3];
            }
            #pragma unroll
            for (int mf = 0; mf < 4; ++mf) {
                uint32_t af[4];
                ldmx4(af, a_b + (uint32_t)mf * (16 * ROWB) + s * 32);
                #pragma unroll
                for (int nf = 0; nf < 4; ++nf)
                    mma16816(acc[mf][nf], af, bf[nf][0], bf[nf][1]);
            }
        }
    }

    if (which == 0) {
        // GEMM1 epilogue: write exp(score), accumulate column sums into g_S.
        __shared__ float scol[128];
        #pragma unroll
        for (int i = tid; i < 128; i += 256) scol[i] = 0.f;
        __syncthreads();

        float csum[8];
        #pragma unroll
        for (int j = 0; j < 8; ++j) csum[j] = 0.f;

        #pragma unroll
        for (int mf = 0; mf < 4; ++mf) {
            const int rr = wm0 + mf * 16 + gid;
            #pragma unroll
            for (int nf = 0; nf < 4; ++nf) {
                const int cc = wn0 + nf * 8 + 2 * tig;
                float e0 = __expf(acc[mf][nf][0]);
                float e1 = __expf(acc[mf][nf][1]);
                float e2 = __expf(acc[mf][nf][2]);
                float e3 = __expf(acc[mf][nf][3]);
                csum[nf * 2 + 0] += e0 + e2;
                csum[nf * 2 + 1] += e1 + e3;
                float2 v0 = make_float2(e0, e1);
                float2 v1 = make_float2(e2, e3);
                *(float2*)(C + (size_t)rr * ldc + cc)       = v0;
                *(float2*)(C + (size_t)(rr + 8) * ldc + cc) = v1;
            }
        }
        #pragma unroll
        for (int nf = 0; nf < 4; ++nf) {
            atomicAdd(&scol[wn0 + nf * 8 + 2 * tig],     csum[nf * 2 + 0]);
            atomicAdd(&scol[wn0 + nf * 8 + 2 * tig + 1], csum[nf * 2 + 1]);
        }
        __syncthreads();
        if (tid < 128)
            atomicAdd(&g_S[(size_t)(z >> bshift) * HW_ + n0 + tid], scol[tid]);
    } else {
        #pragma unroll
        for (int mf = 0; mf < 4; ++mf) {
            const int rr = wm0 + mf * 16 + gid;
            #pragma unroll
            for (int nf = 0; nf < 4; ++nf) {
                const int cc = wn0 + nf * 8 + 2 * tig;
                float2 v0, v1;
                v0.x = acc[mf][nf][0]; v0.y = acc[mf][nf][1];
                v1.x = acc[mf][nf][2]; v1.y = acc[mf][nf][3];
                *(float2*)(C + (size_t)rr * ldc + cc)       = v0;
                *(float2*)(C + (size_t)(rr + 8) * ldc + cc) = v1;
            }
        }
    }
}

// ---------------------------------------------------------------------------
// Normalize + transpose/convert: p *= 1/S (in place) AND emit pT fp16.
// Single pass (exp already applied by GEMM1 epilogue).
// Block: 256 threads, 32 columns (n) x 8-way k split.
// ---------------------------------------------------------------------------
__global__ __launch_bounds__(256) void normalize_pt_kernel(float* __restrict__ p)
{
    const int b  = blockIdx.y;
    const int n0 = blockIdx.x * 32;
    float* col = p + (size_t)b * THW_ * HW_ + n0;

    const int tid = threadIdx.x;
    const int nn = tid & 31;
    const int kk = tid >> 5;   // 0..7

    const float rinv = 1.0f / g_S[(size_t)b * HW_ + n0 + nn];

    __shared__ __align__(16) __half thi[32][72];

    const int wrow = tid >> 3;            // 0..31 (n row for output)
    const int wseg = (tid & 7) * 8;       // k segment within 64-chunk
    const size_t gbase = ((size_t)b * HW_ + n0) * THW_;

    for (int k0 = 0; k0 < THW_; k0 += 64) {
        __align__(16) __half hbuf[8];
        #pragma unroll
        for (int j = 0; j < 8; ++j) {
            const int k = k0 + kk * 8 + j;
            const size_t idx = (size_t)k * HW_ + nn;
            const float e = col[idx] * rinv;
            col[idx] = e;
            hbuf[j] = __float2half(e);
        }
        *(uint4*)&thi[nn][kk * 8] = *(const uint4*)hbuf;
        __syncthreads();

        *(uint4*)(g_pT + gbase + (size_t)wrow * THW_ + k0 + wseg) =
            *(const uint4*)&thi[wrow][wseg];
        __syncthreads();
    }
}

// ---------------------------------------------------------------------------
// Concat epilogue: mem_out[b, 512:1024, :] = q_out[b]
// ---------------------------------------------------------------------------
__global__ __launch_bounds__(256) void copy_qout_kernel(
    const float4* __restrict__ q_out, float4* __restrict__ mem_out)
{
    const int i = blockIdx.x * 256 + threadIdx.x;
    const int per_b = Do_ * HW_ / 4;
    if (i >= B_ * per_b) return;
    const int b = i / per_b;
    const int r = i - b * per_b;
    mem_out[(size_t)b * (2 * Do_ * HW_ / 4) + per_b + r] = q_out[i];
}

// ---------------------------------------------------------------------------
extern "C" void kernel_launch(void* const* d_in, const int* in_sizes, int n_in,
                              void* d_out, int out_size)
{
    const float* m_in  = (const float*)d_in[0];
    const float* m_out = (const float*)d_in[1];
    const float* q_in  = (const float*)d_in[2];
    const float* q_out = (const float*)d_in[3];

    float* out     = (float*)d_out;
    float* mem_out = out;
    float* p       = out + (size_t)B_ * 2 * Do_ * HW_;

    cudaFuncSetAttribute(gemm_fp16, cudaFuncAttributeMaxDynamicSharedMemorySize, GSMEM);

    // 0. zero softmax-sum buffer
    zero_s_kernel<<<B_ * HW_ / 256, 256>>>();

    // 1. convert operands (transpose to K-major where needed)
    conv_mo_kernel<<<(B_ * Do_ * THW_ / 4 + 255) / 256, 256>>>((const float4*)m_out);
    dim3 tb(32, 8);
    tconv_kernel<<<dim3(32, 4, 32), tb>>>(m_in, 128, 1024, 1.0f, 0);
    tconv_kernel<<<dim3(32, 4, 8),  tb>>>(q_in, 128, 1024, SCALE_, 1);

    // 2. GEMM1: exp(scores) -> p region; column sums -> g_S
    gemm_fp16<<<dim3(8, 8, 32), 256, GSMEM>>>(
        p, 128, 1024,
        (unsigned long long)1024 * 128, (unsigned long long)1024 * 128,
        (unsigned long long)HW_ * HW_, 2, 0);

    // 3. normalize (in place) + pT convert/transpose (single pass)
    dim3 gs(HW_ / 32, B_);
    normalize_pt_kernel<<<gs, 256>>>(p);

    // 4. GEMM2: mem -> mem_out channels [0:512]
    gemm_fp16<<<dim3(4, 8, 8), 256, GSMEM>>>(
        mem_out, 4096, 1024,
        (unsigned long long)512 * 4096, (unsigned long long)1024 * 4096,
        (unsigned long long)1024 * 1024, 0, 1);

    // 5. concat q_out
    copy_qout_kernel<<<(B_ * Do_ * HW_ / 4 + 255) / 256, 256>>>(
        (const float4*)q_out, (float4*)mem_out);
}